// round 8
// baseline (speedup 1.0000x reference)
#include <cuda_runtime.h>
#include <cuda.h>
#include <cuda_fp16.h>
#include <cstdint>
#include <cstddef>

// ---------------------------------------------------------------------------
// birealnet binary conv (base sm_103 target, no tcgen05):
//   out = conv3x3_same(x, scale[n]*sign(w)*mask)
// x padded to (32,58,58,256) fp16; weights binarized to fp16 (+-1/0, exact);
// conv = 9 shifted GEMMs via warp-level mma.sync (HMMA), fp32 accumulate.
// PERSISTENT kernel: 296 resident CTAs, each loops over linear M-tiles;
// producer warp streams TMA stages continuously across tile boundaries so
// the pipeline never drains and epilogues overlap with prefetch.
// ---------------------------------------------------------------------------

#define ROWS_PAD   107648          // 32*58*58 = 841 * 128 exactly
#define ROWS_ALLOC 107776          // + 128 slack rows (feed discarded D rows)
#define N_TILES_T  1682            // 841 M-tiles * 2 N-halves
#define GRID_X     296             // 148 SMs * 2 CTAs (all resident)

__device__ __align__(1024) __half g_xh[(size_t)ROWS_ALLOC * 256];
__device__ __align__(1024) __half g_bw[9 * 256 * 256];   // [tap][n][ci]
__device__ float g_scale[256];

// ------------------------------ ptx helpers --------------------------------

__device__ __forceinline__ uint32_t smem_u32(const void* p) {
    uint32_t a;
    asm("{ .reg .u64 t; cvta.to.shared.u64 t, %1; cvt.u32.u64 %0, t; }"
        : "=r"(a) : "l"(p));
    return a;
}

__device__ __forceinline__ void mbar_init(uint32_t mbar, uint32_t cnt) {
    asm volatile("mbarrier.init.shared.b64 [%0], %1;" :: "r"(mbar), "r"(cnt) : "memory");
}
__device__ __forceinline__ void mbar_expect_tx(uint32_t mbar, uint32_t bytes) {
    asm volatile("mbarrier.arrive.expect_tx.shared.b64 _, [%0], %1;"
                 :: "r"(mbar), "r"(bytes) : "memory");
}
__device__ __forceinline__ void mbar_arrive(uint32_t mbar) {
    asm volatile("mbarrier.arrive.shared.b64 _, [%0];" :: "r"(mbar) : "memory");
}
__device__ __forceinline__ void mbar_wait(uint32_t mbar, int parity) {
    asm volatile(
        "{\n\t.reg .pred P1;\n\t"
        "WAIT_LOOP_%=:\n\t"
        "mbarrier.try_wait.parity.acquire.cta.shared::cta.b64 P1, [%0], %1, 0x989680;\n\t"
        "@P1 bra.uni WAIT_DONE_%=;\n\t"
        "bra.uni WAIT_LOOP_%=;\n\t"
        "WAIT_DONE_%=:\n\t}"
        :: "r"(mbar), "r"(parity) : "memory");
}

__device__ __forceinline__ void tma2d(uint32_t dst, const CUtensorMap* tm,
                                      int cx, int cy, uint32_t mbar) {
    asm volatile(
        "cp.async.bulk.tensor.2d.shared::cta.global.tile.mbarrier::complete_tx::bytes "
        "[%0], [%1, {%2, %3}], [%4];"
        :: "r"(dst), "l"(tm), "r"(cx), "r"(cy), "r"(mbar) : "memory");
}

__device__ __forceinline__ void ldsm4(uint32_t* r, uint32_t addr) {
    asm volatile("ldmatrix.sync.aligned.m8n8.x4.shared.b16 {%0,%1,%2,%3}, [%4];"
                 : "=r"(r[0]), "=r"(r[1]), "=r"(r[2]), "=r"(r[3]) : "r"(addr));
}

__device__ __forceinline__ void mma16816(float* d, const uint32_t* a,
                                         uint32_t b0, uint32_t b1) {
    asm volatile(
        "mma.sync.aligned.m16n8k16.row.col.f32.f16.f16.f32 "
        "{%0,%1,%2,%3}, {%4,%5,%6,%7}, {%8,%9}, {%0,%1,%2,%3};"
        : "+f"(d[0]), "+f"(d[1]), "+f"(d[2]), "+f"(d[3])
        : "r"(a[0]), "r"(a[1]), "r"(a[2]), "r"(a[3]), "r"(b0), "r"(b1));
}

// ------------------------------ fused prep ---------------------------------

#define PAD_BLOCKS  13456     // 107648 rows / 8 per block
#define BIN_BLOCKS  2304
#define SCL_BLOCKS  256
#define PREP_GRID   (PAD_BLOCKS + BIN_BLOCKS + SCL_BLOCKS)

__global__ void k_prep(const float* __restrict__ x, const float* __restrict__ w,
                       const float* __restrict__ mask) {
    int bx = blockIdx.x, t = threadIdx.x;
    if (bx < PAD_BLOCKS) {
        // pad + fp32->fp16: 8 rows per block, 8 channels per thread
        int row = bx * 8 + (t >> 5);
        int c8  = (t & 31) << 3;
        float4 v0 = make_float4(0.f, 0.f, 0.f, 0.f);
        float4 v1 = v0;
        int bi  = row / 3364;
        int rem = row - bi * 3364;
        int hp  = rem / 58, wp = rem - hp * 58;
        if (hp >= 1 && hp <= 56 && wp >= 1 && wp <= 56) {
            const float* src = x + (((size_t)((bi * 56 + hp - 1) * 56) + (wp - 1)) * 256 + c8);
            v0 = *(const float4*)(src);
            v1 = *(const float4*)(src + 4);
        }
        union { __half h[8]; uint4 u; } H;
        H.h[0] = __float2half_rn(v0.x); H.h[1] = __float2half_rn(v0.y);
        H.h[2] = __float2half_rn(v0.z); H.h[3] = __float2half_rn(v0.w);
        H.h[4] = __float2half_rn(v1.x); H.h[5] = __float2half_rn(v1.y);
        H.h[6] = __float2half_rn(v1.z); H.h[7] = __float2half_rn(v1.w);
        *(uint4*)(g_xh + (size_t)row * 256 + c8) = H.u;
    } else if (bx < PAD_BLOCKS + BIN_BLOCKS) {
        int idx = (bx - PAD_BLOCKS) * 256 + t;   // [0, 589824): [tap][n][ci]
        int ci = idx & 255;
        int n  = (idx >> 8) & 255;
        int tp = idx >> 16;
        size_t wi = ((size_t)(tp * 256 + ci)) * 256 + n;
        float wv = w[wi];
        float sg = (wv > 0.f) ? 1.f : ((wv < 0.f) ? -1.f : 0.f);
        g_bw[idx] = __float2half_rn(sg * mask[wi]);
    } else {
        __shared__ float red[256];
        int n = bx - PAD_BLOCKS - BIN_BLOCKS;
        float s = 0.f;
        for (int r = t; r < 2304; r += 256) s += fabsf(w[(size_t)r * 256 + n]);
        red[t] = s;
        __syncthreads();
        for (int o = 128; o > 0; o >>= 1) {
            if (t < o) red[t] += red[t + o];
            __syncthreads();
        }
        if (t == 0) g_scale[n] = red[0] * (1.0f / 2304.0f);
    }
}

// ------------------------------ main kernel --------------------------------

#define STAGE_SZ 32768       // A 16K + B 16K
#define OFF_B    16384
#define NSTAGE   3
#define CTRL     98304       // 3 * STAGE_SZ
#define SMEM_DYN (CTRL + 64 + 1024 + 1024)   // mbarriers + scl + align slack
#define NTHREADS 288          // 8 consumer warps + 1 producer warp

__global__ void __launch_bounds__(NTHREADS, 2)
k_conv(const __grid_constant__ CUtensorMap tm_x,
       const __grid_constant__ CUtensorMap tm_w,
       float* __restrict__ out) {
    extern __shared__ char smem_raw[];
    uint32_t raw  = smem_u32(smem_raw);
    uint32_t base = (raw + 1023) & ~1023u;
    char*    sb   = smem_raw + (base - raw);

    int tid = threadIdx.x, wid = tid >> 5, lane = tid & 31;

    float* scl = (float*)(sb + CTRL + 64);
    if (tid < 256) scl[tid] = g_scale[tid];

    uint32_t mb = base + CTRL;                   // full[s]=mb+8s, empty[s]=mb+24+8s
    if (tid == 0) {
        #pragma unroll
        for (int s = 0; s < NSTAGE; s++) {
            mbar_init(mb + 8 * s, 1);            // full: 1 tx-producer
            mbar_init(mb + 24 + 8 * s, 8);       // empty: 8 consumer warps
        }
        asm volatile("fence.proxy.async.shared::cta;" ::: "memory");
    }
    __syncthreads();

    // =============== producer warp (warp 8) ===============
    // Continuous stage stream across all tiles owned by this CTA.
    if (wid == 8) {
        if (lane == 0) {
            int s = 0, pe = 0;
            long g = 0;                          // global stage counter
            for (int tile = blockIdx.x; tile < N_TILES_T; tile += GRID_X) {
                int r0 = (tile >> 1) << 7;
                int n0 = (tile & 1) << 7;
                for (int i = 0; i < 36; i++, g++) {
                    if (g >= NSTAGE) mbar_wait(mb + 24 + 8 * s, pe);
                    int t9 = i >> 2, kc = (i & 3) << 6;
                    int kh = t9 / 3, kw = t9 - kh * 3;
                    uint32_t fb = mb + 8 * s;
                    mbar_expect_tx(fb, STAGE_SZ);
                    tma2d(base + s * STAGE_SZ,         &tm_x, kc, r0 + kh * 58 + kw, fb);
                    tma2d(base + s * STAGE_SZ + OFF_B, &tm_w, kc, t9 * 256 + n0,     fb);
                    if (++s == NSTAGE) { s = 0; if (g >= NSTAGE) pe ^= 1; }
                }
            }
        }
        return;                                  // producer warp exits
    }

    // =============== consumer warps (0-7) ===============
    int warp_m = (wid & 3) << 5;                 // 0,32,64,96
    int warp_n = (wid >> 2) << 6;                // 0,64
    int rA = (lane & 7) | (((lane >> 3) & 1) << 3);        // ldmatrix row in 16
    int cbase = (((lane >> 4) << 4) ^ ((lane & 7) << 4));  // swizzled col base

    uint32_t aoff0 = (uint32_t)(warp_m + rA) * 128;
    uint32_t aoff1 = aoff0 + 16 * 128;
    uint32_t boff[4];
    #pragma unroll
    for (int nb = 0; nb < 4; nb++) boff[nb] = (uint32_t)(warp_n + nb * 16 + rA) * 128;

    int r4 = lane >> 2;                          // epilogue row within 8
    int c2 = (lane & 3) << 1;                    // epilogue col pair

    int s = 0, ph = 0;                           // continuous across tiles
    for (int tile = blockIdx.x; tile < N_TILES_T; tile += GRID_X) {
        int r0 = (tile >> 1) << 7;
        int n0 = (tile & 1) << 7;

        float acc[2][8][4];
        #pragma unroll
        for (int a = 0; a < 2; a++)
            #pragma unroll
            for (int nt = 0; nt < 8; nt++)
                #pragma unroll
                for (int c = 0; c < 4; c++) acc[a][nt][c] = 0.f;

        for (int i = 0; i < 36; i++) {
            mbar_wait(mb + 8 * s, ph);
            uint32_t Ab = base + s * STAGE_SZ;
            uint32_t Bb = Ab + OFF_B;

            #pragma unroll
            for (int kk = 0; kk < 4; kk++) {
                uint32_t colx = ((uint32_t)kk << 5) ^ (uint32_t)cbase;
                uint32_t a0[4], a1[4], bb[4][4];
                ldsm4(a0, Ab + aoff0 + colx);
                ldsm4(a1, Ab + aoff1 + colx);
                #pragma unroll
                for (int nb = 0; nb < 4; nb++) ldsm4(bb[nb], Bb + boff[nb] + colx);
                #pragma unroll
                for (int nb = 0; nb < 4; nb++) {
                    mma16816(acc[0][nb * 2],     a0, bb[nb][0], bb[nb][2]);
                    mma16816(acc[0][nb * 2 + 1], a0, bb[nb][1], bb[nb][3]);
                    mma16816(acc[1][nb * 2],     a1, bb[nb][0], bb[nb][2]);
                    mma16816(acc[1][nb * 2 + 1], a1, bb[nb][1], bb[nb][3]);
                }
            }
            if (lane == 0) mbar_arrive(mb + 24 + 8 * s);   // stage consumed
            if (++s == NSTAGE) { s = 0; ph ^= 1; }
        }

        // ---- epilogue: per-row (b,hp,wp) decode, scale + store ----
        // (producer is already fetching the next tile into freed stages)
        #pragma unroll
        for (int mt = 0; mt < 2; mt++) {
            #pragma unroll
            for (int half = 0; half < 2; half++) {
                int p = warp_m + mt * 16 + r4 + half * 8;
                int r = r0 + p;
                int bi  = r / 3364;              // 58*58
                int rem = r - bi * 3364;
                int hp  = rem / 58, wp = rem - hp * 58;
                if (hp >= 56 || wp >= 56) continue;
                size_t ob = (((size_t)(bi * 56 + hp)) * 56 + wp) * 256;
                #pragma unroll
                for (int nt = 0; nt < 8; nt++) {
                    int ng = n0 + warp_n + nt * 8 + c2;
                    float2 v;
                    v.x = acc[mt][nt][half * 2 + 0] * scl[ng];
                    v.y = acc[mt][nt][half * 2 + 1] * scl[ng + 1];
                    *(float2*)(out + ob + ng) = v;
                }
            }
        }
    }
}

// ------------------------------ host side ----------------------------------

typedef CUresult (CUDAAPI *tmap_encode_fn)(
    CUtensorMap*, CUtensorMapDataType, cuuint32_t, void*,
    const cuuint64_t*, const cuuint64_t*, const cuuint32_t*, const cuuint32_t*,
    CUtensorMapInterleave, CUtensorMapSwizzle, CUtensorMapL2promotion,
    CUtensorMapFloatOOBfill);

static void encode_f16_2d(tmap_encode_fn enc, CUtensorMap* tm, void* gptr,
                          uint64_t d0, uint64_t d1, uint32_t b0, uint32_t b1) {
    cuuint64_t dims[2]    = {d0, d1};
    cuuint64_t strides[1] = {d0 * 2};            // bytes
    cuuint32_t box[2]     = {b0, b1};
    cuuint32_t estr[2]    = {1, 1};
    enc(tm, CU_TENSOR_MAP_DATA_TYPE_FLOAT16, 2, gptr, dims, strides, box, estr,
        CU_TENSOR_MAP_INTERLEAVE_NONE, CU_TENSOR_MAP_SWIZZLE_128B,
        CU_TENSOR_MAP_L2_PROMOTION_L2_128B, CU_TENSOR_MAP_FLOAT_OOB_FILL_NONE);
}

extern "C" void kernel_launch(void* const* d_in, const int* in_sizes, int n_in,
                              void* d_out, int out_size) {
    const float* x    = (const float*)d_in[0];
    const float* w    = (const float*)d_in[1];
    const float* mask = (const float*)d_in[2];
    float* out = (float*)d_out;

    tmap_encode_fn enc = nullptr;
    cudaDriverEntryPointQueryResult qr;
    cudaGetDriverEntryPointByVersion("cuTensorMapEncodeTiled", (void**)&enc,
                                     12000, cudaEnableDefault, &qr);
    if (!enc) return;  // visible failure: no work captured

    void *p_xh = nullptr, *p_bw = nullptr;
    cudaGetSymbolAddress(&p_xh, g_xh);
    cudaGetSymbolAddress(&p_bw, g_bw);

    CUtensorMap tm_x, tm_w;
    encode_f16_2d(enc, &tm_x, p_xh, 256, ROWS_ALLOC, 64, 128);
    encode_f16_2d(enc, &tm_w, p_bw, 256, 9 * 256, 64, 128);

    k_prep<<<PREP_GRID, 256>>>(x, w, mask);

    cudaFuncSetAttribute(k_conv, cudaFuncAttributeMaxDynamicSharedMemorySize, SMEM_DYN);
    k_conv<<<GRID_X, NTHREADS, SMEM_DYN>>>(tm_x, tm_w, out);
}

// round 9
// speedup vs baseline: 1.0988x; 1.0988x over previous
#include <cuda_runtime.h>
#include <cuda.h>
#include <cuda_fp16.h>
#include <cstdint>
#include <cstddef>

// ---------------------------------------------------------------------------
// birealnet binary conv (base sm_103 target, no tcgen05):
//   out = conv3x3_same(x, scale[n]*sign(w)*mask)
// x padded to (32,58,58,256) fp16; weights binarized to fp16 (+-1/0, exact);
// conv = 9 shifted GEMMs via warp-level mma.sync (HMMA), fp32 accumulate.
// Non-persistent grid (1682 CTAs) -- R8 showed persistence loses inter-CTA
// overlap. Warp-specialized TMA producer, 3-stage pipeline, EARLY empty-
// arrive (stage freed right after last ldmatrix, before the MMA chain).
// ---------------------------------------------------------------------------

#define ROWS_PAD   107648          // 32*58*58 = 841 * 128 exactly
#define ROWS_ALLOC 107776          // + 128 slack rows (feed discarded D rows)
#define N_TILES_T  1682            // 841 M-tiles * 2 N-halves
#define GRID_X     1682

__device__ __align__(1024) __half g_xh[(size_t)ROWS_ALLOC * 256];
__device__ __align__(1024) __half g_bw[9 * 256 * 256];   // [tap][n][ci]
__device__ float g_scale[256];

// ------------------------------ ptx helpers --------------------------------

__device__ __forceinline__ uint32_t smem_u32(const void* p) {
    uint32_t a;
    asm("{ .reg .u64 t; cvta.to.shared.u64 t, %1; cvt.u32.u64 %0, t; }"
        : "=r"(a) : "l"(p));
    return a;
}

__device__ __forceinline__ void mbar_init(uint32_t mbar, uint32_t cnt) {
    asm volatile("mbarrier.init.shared.b64 [%0], %1;" :: "r"(mbar), "r"(cnt) : "memory");
}
__device__ __forceinline__ void mbar_expect_tx(uint32_t mbar, uint32_t bytes) {
    asm volatile("mbarrier.arrive.expect_tx.shared.b64 _, [%0], %1;"
                 :: "r"(mbar), "r"(bytes) : "memory");
}
__device__ __forceinline__ void mbar_arrive(uint32_t mbar) {
    asm volatile("mbarrier.arrive.shared.b64 _, [%0];" :: "r"(mbar) : "memory");
}
__device__ __forceinline__ void mbar_wait(uint32_t mbar, int parity) {
    asm volatile(
        "{\n\t.reg .pred P1;\n\t"
        "WAIT_LOOP_%=:\n\t"
        "mbarrier.try_wait.parity.acquire.cta.shared::cta.b64 P1, [%0], %1, 0x989680;\n\t"
        "@P1 bra.uni WAIT_DONE_%=;\n\t"
        "bra.uni WAIT_LOOP_%=;\n\t"
        "WAIT_DONE_%=:\n\t}"
        :: "r"(mbar), "r"(parity) : "memory");
}

__device__ __forceinline__ void tma2d(uint32_t dst, const CUtensorMap* tm,
                                      int cx, int cy, uint32_t mbar) {
    asm volatile(
        "cp.async.bulk.tensor.2d.shared::cta.global.tile.mbarrier::complete_tx::bytes "
        "[%0], [%1, {%2, %3}], [%4];"
        :: "r"(dst), "l"(tm), "r"(cx), "r"(cy), "r"(mbar) : "memory");
}

__device__ __forceinline__ void ldsm4(uint32_t* r, uint32_t addr) {
    asm volatile("ldmatrix.sync.aligned.m8n8.x4.shared.b16 {%0,%1,%2,%3}, [%4];"
                 : "=r"(r[0]), "=r"(r[1]), "=r"(r[2]), "=r"(r[3]) : "r"(addr));
}

__device__ __forceinline__ void mma16816(float* d, const uint32_t* a,
                                         uint32_t b0, uint32_t b1) {
    asm volatile(
        "mma.sync.aligned.m16n8k16.row.col.f32.f16.f16.f32 "
        "{%0,%1,%2,%3}, {%4,%5,%6,%7}, {%8,%9}, {%0,%1,%2,%3};"
        : "+f"(d[0]), "+f"(d[1]), "+f"(d[2]), "+f"(d[3])
        : "r"(a[0]), "r"(a[1]), "r"(a[2]), "r"(a[3]), "r"(b0), "r"(b1));
}

// ------------------------------ fused prep ---------------------------------

#define PAD_BLOCKS  13456     // 107648 rows / 8 per block
#define BIN_BLOCKS  2304
#define SCL_BLOCKS  256
#define PREP_GRID   (PAD_BLOCKS + BIN_BLOCKS + SCL_BLOCKS)

__global__ void k_prep(const float* __restrict__ x, const float* __restrict__ w,
                       const float* __restrict__ mask) {
    int bx = blockIdx.x, t = threadIdx.x;
    if (bx < PAD_BLOCKS) {
        // pad + fp32->fp16: 8 rows per block, 8 channels per thread
        int row = bx * 8 + (t >> 5);
        int c8  = (t & 31) << 3;
        float4 v0 = make_float4(0.f, 0.f, 0.f, 0.f);
        float4 v1 = v0;
        int bi  = row / 3364;
        int rem = row - bi * 3364;
        int hp  = rem / 58, wp = rem - hp * 58;
        if (hp >= 1 && hp <= 56 && wp >= 1 && wp <= 56) {
            const float* src = x + (((size_t)((bi * 56 + hp - 1) * 56) + (wp - 1)) * 256 + c8);
            v0 = *(const float4*)(src);
            v1 = *(const float4*)(src + 4);
        }
        union { __half h[8]; uint4 u; } H;
        H.h[0] = __float2half_rn(v0.x); H.h[1] = __float2half_rn(v0.y);
        H.h[2] = __float2half_rn(v0.z); H.h[3] = __float2half_rn(v0.w);
        H.h[4] = __float2half_rn(v1.x); H.h[5] = __float2half_rn(v1.y);
        H.h[6] = __float2half_rn(v1.z); H.h[7] = __float2half_rn(v1.w);
        *(uint4*)(g_xh + (size_t)row * 256 + c8) = H.u;
    } else if (bx < PAD_BLOCKS + BIN_BLOCKS) {
        int idx = (bx - PAD_BLOCKS) * 256 + t;   // [0, 589824): [tap][n][ci]
        int ci = idx & 255;
        int n  = (idx >> 8) & 255;
        int tp = idx >> 16;
        size_t wi = ((size_t)(tp * 256 + ci)) * 256 + n;
        float wv = w[wi];
        float sg = (wv > 0.f) ? 1.f : ((wv < 0.f) ? -1.f : 0.f);
        g_bw[idx] = __float2half_rn(sg * mask[wi]);
    } else {
        __shared__ float red[256];
        int n = bx - PAD_BLOCKS - BIN_BLOCKS;
        float s = 0.f;
        for (int r = t; r < 2304; r += 256) s += fabsf(w[(size_t)r * 256 + n]);
        red[t] = s;
        __syncthreads();
        for (int o = 128; o > 0; o >>= 1) {
            if (t < o) red[t] += red[t + o];
            __syncthreads();
        }
        if (t == 0) g_scale[n] = red[0] * (1.0f / 2304.0f);
    }
}

// ------------------------------ main kernel --------------------------------

#define STAGE_SZ 32768       // A 16K + B 16K
#define OFF_B    16384
#define NSTAGE   3
#define CTRL     98304       // 3 * STAGE_SZ
#define SMEM_DYN (CTRL + 64 + 1024 + 1024)   // mbarriers + scl + align slack
#define NTHREADS 288          // 8 consumer warps + 1 producer warp

__global__ void __launch_bounds__(NTHREADS, 2)
k_conv(const __grid_constant__ CUtensorMap tm_x,
       const __grid_constant__ CUtensorMap tm_w,
       float* __restrict__ out) {
    extern __shared__ char smem_raw[];
    uint32_t raw  = smem_u32(smem_raw);
    uint32_t base = (raw + 1023) & ~1023u;
    char*    sb   = smem_raw + (base - raw);

    int tid = threadIdx.x, wid = tid >> 5, lane = tid & 31;
    int r0 = (blockIdx.x >> 1) << 7;             // tile base padded row
    int n0 = (blockIdx.x & 1) << 7;              // 0 or 128

    float* scl = (float*)(sb + CTRL + 64);
    if (tid < 256) scl[tid] = g_scale[tid];

    uint32_t mb = base + CTRL;                   // full[s]=mb+8s, empty[s]=mb+24+8s
    if (tid == 0) {
        #pragma unroll
        for (int s = 0; s < NSTAGE; s++) {
            mbar_init(mb + 8 * s, 1);            // full: 1 tx-producer
            mbar_init(mb + 24 + 8 * s, 8);       // empty: 8 consumer warps
        }
        asm volatile("fence.proxy.async.shared::cta;" ::: "memory");
    }
    __syncthreads();

    // =============== producer warp (warp 8) ===============
    if (wid == 8) {
        if (lane == 0) {
            int s = 0, pe = 0;
            for (int i = 0; i < 36; i++) {
                if (i >= NSTAGE) mbar_wait(mb + 24 + 8 * s, pe);
                int t9 = i >> 2, kc = (i & 3) << 6;
                int kh = t9 / 3, kw = t9 - kh * 3;
                uint32_t fb = mb + 8 * s;
                mbar_expect_tx(fb, STAGE_SZ);
                tma2d(base + s * STAGE_SZ,         &tm_x, kc, r0 + kh * 58 + kw, fb);
                tma2d(base + s * STAGE_SZ + OFF_B, &tm_w, kc, t9 * 256 + n0,     fb);
                if (++s == NSTAGE) { s = 0; if (i >= NSTAGE) pe ^= 1; }
            }
        }
        return;                                  // producer warp exits
    }

    // =============== consumer warps (0-7) ===============
    int warp_m = (wid & 3) << 5;                 // 0,32,64,96
    int warp_n = (wid >> 2) << 6;                // 0,64
    int rA = (lane & 7) | (((lane >> 3) & 1) << 3);        // ldmatrix row in 16
    int cbase = (((lane >> 4) << 4) ^ ((lane & 7) << 4));  // swizzled col base

    uint32_t aoff0 = (uint32_t)(warp_m + rA) * 128;
    uint32_t aoff1 = aoff0 + 16 * 128;
    uint32_t boff[4];
    #pragma unroll
    for (int nb = 0; nb < 4; nb++) boff[nb] = (uint32_t)(warp_n + nb * 16 + rA) * 128;

    float acc[2][8][4];
    #pragma unroll
    for (int a = 0; a < 2; a++)
        #pragma unroll
        for (int nt = 0; nt < 8; nt++)
            #pragma unroll
            for (int c = 0; c < 4; c++) acc[a][nt][c] = 0.f;

    int s = 0, ph = 0;
    for (int i = 0; i < 36; i++) {
        mbar_wait(mb + 8 * s, ph);
        uint32_t Ab = base + s * STAGE_SZ;
        uint32_t Bb = Ab + OFF_B;

        #pragma unroll
        for (int kk = 0; kk < 4; kk++) {
            uint32_t colx = ((uint32_t)kk << 5) ^ (uint32_t)cbase;
            uint32_t a0[4], a1[4], bb[4][4];
            ldsm4(a0, Ab + aoff0 + colx);
            ldsm4(a1, Ab + aoff1 + colx);
            #pragma unroll
            for (int nb = 0; nb < 4; nb++) ldsm4(bb[nb], Bb + boff[nb] + colx);
            // stage smem is dead after the last ldmatrix of kk=3: free it
            // before the MMA chain so the producer refills ~1.5k cyc earlier.
            if (kk == 3 && lane == 0) mbar_arrive(mb + 24 + 8 * s);
            #pragma unroll
            for (int nb = 0; nb < 4; nb++) {
                mma16816(acc[0][nb * 2],     a0, bb[nb][0], bb[nb][2]);
                mma16816(acc[0][nb * 2 + 1], a0, bb[nb][1], bb[nb][3]);
                mma16816(acc[1][nb * 2],     a1, bb[nb][0], bb[nb][2]);
                mma16816(acc[1][nb * 2 + 1], a1, bb[nb][1], bb[nb][3]);
            }
        }
        if (++s == NSTAGE) { s = 0; ph ^= 1; }
    }

    // ---- epilogue: per-row (b,hp,wp) decode, scale + store ----
    int r4 = lane >> 2;                          // 0..7
    int c2 = (lane & 3) << 1;                    // 0,2,4,6
    #pragma unroll
    for (int mt = 0; mt < 2; mt++) {
        #pragma unroll
        for (int half = 0; half < 2; half++) {
            int p = warp_m + mt * 16 + r4 + half * 8;
            int r = r0 + p;
            int bi  = r / 3364;                  // 58*58
            int rem = r - bi * 3364;
            int hp  = rem / 58, wp = rem - hp * 58;
            if (hp >= 56 || wp >= 56) continue;  // invalid output position
            size_t ob = (((size_t)(bi * 56 + hp)) * 56 + wp) * 256;
            #pragma unroll
            for (int nt = 0; nt < 8; nt++) {
                int ng = n0 + warp_n + nt * 8 + c2;
                float2 v;
                v.x = acc[mt][nt][half * 2 + 0] * scl[ng];
                v.y = acc[mt][nt][half * 2 + 1] * scl[ng + 1];
                *(float2*)(out + ob + ng) = v;
            }
        }
    }
}

// ------------------------------ host side ----------------------------------

typedef CUresult (CUDAAPI *tmap_encode_fn)(
    CUtensorMap*, CUtensorMapDataType, cuuint32_t, void*,
    const cuuint64_t*, const cuuint64_t*, const cuuint32_t*, const cuuint32_t*,
    CUtensorMapInterleave, CUtensorMapSwizzle, CUtensorMapL2promotion,
    CUtensorMapFloatOOBfill);

static void encode_f16_2d(tmap_encode_fn enc, CUtensorMap* tm, void* gptr,
                          uint64_t d0, uint64_t d1, uint32_t b0, uint32_t b1) {
    cuuint64_t dims[2]    = {d0, d1};
    cuuint64_t strides[1] = {d0 * 2};            // bytes
    cuuint32_t box[2]     = {b0, b1};
    cuuint32_t estr[2]    = {1, 1};
    enc(tm, CU_TENSOR_MAP_DATA_TYPE_FLOAT16, 2, gptr, dims, strides, box, estr,
        CU_TENSOR_MAP_INTERLEAVE_NONE, CU_TENSOR_MAP_SWIZZLE_128B,
        CU_TENSOR_MAP_L2_PROMOTION_L2_128B, CU_TENSOR_MAP_FLOAT_OOB_FILL_NONE);
}

extern "C" void kernel_launch(void* const* d_in, const int* in_sizes, int n_in,
                              void* d_out, int out_size) {
    const float* x    = (const float*)d_in[0];
    const float* w    = (const float*)d_in[1];
    const float* mask = (const float*)d_in[2];
    float* out = (float*)d_out;

    tmap_encode_fn enc = nullptr;
    cudaDriverEntryPointQueryResult qr;
    cudaGetDriverEntryPointByVersion("cuTensorMapEncodeTiled", (void**)&enc,
                                     12000, cudaEnableDefault, &qr);
    if (!enc) return;  // visible failure: no work captured

    void *p_xh = nullptr, *p_bw = nullptr;
    cudaGetSymbolAddress(&p_xh, g_xh);
    cudaGetSymbolAddress(&p_bw, g_bw);

    CUtensorMap tm_x, tm_w;
    encode_f16_2d(enc, &tm_x, p_xh, 256, ROWS_ALLOC, 64, 128);
    encode_f16_2d(enc, &tm_w, p_bw, 256, 9 * 256, 64, 128);

    k_prep<<<PREP_GRID, 256>>>(x, w, mask);

    cudaFuncSetAttribute(k_conv, cudaFuncAttributeMaxDynamicSharedMemorySize, SMEM_DYN);
    k_conv<<<GRID_X, NTHREADS, SMEM_DYN>>>(tm_x, tm_w, out);
}